// round 6
// baseline (speedup 1.0000x reference)
#include <cuda_runtime.h>
#include <cstdint>

#define N_  4
#define C_  128
#define H_  128
#define W_  128
#define OC  8
#define OH  256
#define OW  256
#define HW  (H_*W_)

typedef unsigned long long ull;

// Per-channel-group partial conv outputs: [cg][n][o][h][w]
__device__ float g_part[4][N_*OC*H_*W_];

// ---- f32x2 helpers ----
__device__ __forceinline__ ull pack2(float lo, float hi) {
    ull r;
    asm("mov.b64 %0, {%1, %2};" : "=l"(r) : "f"(lo), "f"(hi));
    return r;
}
__device__ __forceinline__ void unpack2(ull v, float& lo, float& hi) {
    asm("mov.b64 {%0, %1}, %2;" : "=f"(lo), "=f"(hi) : "l"(v));
}
__device__ __forceinline__ ull fma2(ull a, ull b, ull c) {
    ull d;
    asm("fma.rn.f32x2 %0, %1, %2, %3;" : "=l"(d) : "l"(a), "l"(b), "l"(c));
    return d;
}

// ---------------------------------------------------------------------------
// Kernel 1: 3x3 SAME conv, 32-channel partial per block. (round-2 measured-best)
// 256 threads, 32x32 tile, thread = 1 col x 4-row strip, f32x2 row pairs.
// Grid (4,4,16), bz = n*4+cg.
// ---------------------------------------------------------------------------
__global__ __launch_bounds__(256) void conv_part_kernel(
    const float* __restrict__ x,
    const float* __restrict__ wt,    // [o][c][3][3]
    const float* __restrict__ bs)    // [o]
{
    __shared__ float xs[8*34*34];                 // 8 channels, 34x34 halo tile
    __shared__ ull ws2[8*9*8];                    // [cc][tap][o], weight duplicated {w,w}

    const int tid = threadIdx.x;
    const int n  = blockIdx.z >> 2;
    const int cg = blockIdx.z & 3;
    const int h0 = blockIdx.y * 32;
    const int w0 = blockIdx.x * 32;
    const int tx  = tid & 31;
    const int ty0 = (tid >> 5) * 4;

    ull a01[OC], a23[OC];
    if (cg == 0) {
#pragma unroll
        for (int o = 0; o < OC; o++) {
            float b = __ldg(&bs[o]);
            a01[o] = pack2(b, b);
            a23[o] = a01[o];
        }
    } else {
#pragma unroll
        for (int o = 0; o < OC; o++) { a01[o] = 0ull; a23[o] = 0ull; }
    }

    const float* xn = x + ((size_t)n*C_ + cg*32) * HW;

    for (int ch = 0; ch < 4; ch++) {
        const int c0 = ch * 8;
        __syncthreads();
        // Stage chunk weights (duplicated to f32x2)
        for (int i = tid; i < 8*9*8; i += 256) {
            int cc = i / 72;
            int r  = i - cc*72;
            int tap = r >> 3;
            int o   = r & 7;
            float wv = wt[((size_t)o*C_ + (cg*32 + c0 + cc))*9 + tap];
            ws2[i] = pack2(wv, wv);
        }
        // Stage 8 channels of 34x34 halo tile (zero padded)
        for (int i = tid; i < 8*34*34; i += 256) {
            int cc = i / 1156;
            int r  = i - cc*1156;
            int ly = r / 34;
            int lx = r - ly*34;
            int gy = h0 - 1 + ly;
            int gx = w0 - 1 + lx;
            float v = 0.f;
            if ((unsigned)gy < H_ && (unsigned)gx < W_)
                v = xn[(c0+cc)*HW + gy*W_ + gx];
            xs[i] = v;
        }
        __syncthreads();

#pragma unroll
        for (int cc = 0; cc < 8; cc++) {
            const float* xb = &xs[cc*1156 + ty0*34 + tx];
#pragma unroll
            for (int kx = 0; kx < 3; kx++) {
                float v[6];
#pragma unroll
                for (int r = 0; r < 6; r++)
                    v[r] = xb[r*34 + kx];
#pragma unroll
                for (int ky = 0; ky < 3; ky++) {
                    ull p01 = pack2(v[ky],   v[ky+1]);
                    ull p23 = pack2(v[ky+2], v[ky+3]);
                    const ull* wp = &ws2[cc*72 + (ky*3 + kx)*8];
#pragma unroll
                    for (int o = 0; o < OC; o++) {
                        ull w2 = wp[o];
                        a01[o] = fma2(p01, w2, a01[o]);
                        a23[o] = fma2(p23, w2, a23[o]);
                    }
                }
            }
        }
    }

    const int w = w0 + tx;
    float* gp = g_part[cg];
#pragma unroll
    for (int o = 0; o < OC; o++) {
        float r0, r1, r2, r3;
        unpack2(a01[o], r0, r1);
        unpack2(a23[o], r2, r3);
        size_t base = (((size_t)n*OC + o)*H_ + (h0 + ty0))*W_ + w;
        gp[base        ] = r0;
        gp[base +   W_ ] = r1;
        gp[base + 2*W_ ] = r2;
        gp[base + 3*W_ ] = r3;
    }
}

// ---------------------------------------------------------------------------
// Kernel 2: bilinear sampling + pixel shuffle, smem row-staged.
// One block per (n, h), 512 threads = 128 w x 2 kw x 2 kh.
// Per channel: stage x rows [h-3, h+4] (double-buffered, coalesced LDG),
// 4 LDS gathers + 1 coalesced STG. Rare out-of-window samples fall back
// to a predicated __ldg (correctness for arbitrary offsets).
// ---------------------------------------------------------------------------
#define RPAD 132
#define NROWS 8

__global__ __launch_bounds__(512) void sample_kernel(
    const float* __restrict__ x,
    float* __restrict__ out)
{
    __shared__ float soff[OC][W_];
    __shared__ float rows[2][NROWS*RPAD];

    const int b = blockIdx.x;
    const int n = b >> 7;
    const int h = b & (H_-1);
    const int tid = threadIdx.x;

    // Stage offsets for row h (sum of 4 conv partials)
    for (int i = tid; i < OC*W_; i += 512) {
        int o  = i >> 7;
        int ww = i & (W_-1);
        size_t idx = (((size_t)n*OC + o)*H_ + h)*W_ + ww;
        soff[o][ww] = g_part[0][idx] + g_part[1][idx] + g_part[2][idx] + g_part[3][idx];
    }

    const int kw = tid & 1;
    const int w  = (tid >> 1) & (W_-1);
    const int kh = tid >> 8;

    // Staging geometry (constant across channels)
    const int sr = tid >> 6;           // staged row 0..7
    const int sc = (tid & 63) * 2;     // column pair
    const int sgy = h - 3 + sr;        // global row for this thread's stage slot
    const bool srow_ok = ((unsigned)sgy < H_);
    const int stage_off = sr*RPAD + sc;
    const size_t stage_src = (size_t)sgy*W_ + sc;

    const float* xn = x + (size_t)n*C_*HW;

    // Stage channel 0 into buffer 0
    {
        float2 v = srow_ok ? *reinterpret_cast<const float2*>(xn + stage_src)
                           : make_float2(0.f, 0.f);
        *reinterpret_cast<float2*>(&rows[0][stage_off]) = v;
    }
    __syncthreads();

    // Per-thread sample geometry
    const int ob = (kh*2 + kw)*2;
    float sy = (float)h + soff[ob  ][w];
    float sx = (float)w + soff[ob+1][w];
    float y0f = floorf(sy), x0f = floorf(sx);
    int   y0 = (int)y0f,   x0 = (int)x0f;
    float fy = sy - y0f,   fx = sx - x0f;

    float cw0 = (1.f - fy) * (1.f - fx);
    float cw1 = (1.f - fy) * fx;
    float cw2 = fy * (1.f - fx);
    float cw3 = fy * fx;

    const int xl = min(max(x0,     0), W_-1);
    const int xr = min(max(x0 + 1, 0), W_-1);
    if (!((unsigned)x0       < (unsigned)W_)) { cw0 = 0.f; cw2 = 0.f; }
    if (!((unsigned)(x0 + 1) < (unsigned)W_)) { cw1 = 0.f; cw3 = 0.f; }

    const int yt = y0, yb = y0 + 1;
    if (!((unsigned)yt < (unsigned)H_)) { cw0 = 0.f; cw1 = 0.f; }
    if (!((unsigned)yb < (unsigned)H_)) { cw2 = 0.f; cw3 = 0.f; }

    int rst = min(max(yt - (h-3), 0), NROWS-1);
    int rsb = min(max(yb - (h-3), 0), NROWS-1);
    // fallback needed only if true row is inside image but outside staged window
    const bool ft = (yt != h-3+rst) && ((unsigned)yt < (unsigned)H_);
    const bool fb = (yb != h-3+rsb) && ((unsigned)yb < (unsigned)H_);
    const int tl = rst*RPAD + xl, tr = rst*RPAD + xr;
    const int bl = rsb*RPAD + xl, br = rsb*RPAD + xr;

    float* op = out + ((size_t)n*C_)*OH*OW + (size_t)(2*h + kh)*OW + (2*w + kw);

    for (int c = 0; c < C_; c++) {
        const int buf = c & 1;
        // Prefetch-stage next channel into the other buffer
        if (c + 1 < C_) {
            float2 v = srow_ok
                ? *reinterpret_cast<const float2*>(xn + (size_t)(c+1)*HW + stage_src)
                : make_float2(0.f, 0.f);
            *reinterpret_cast<float2*>(&rows[buf ^ 1][stage_off]) = v;
        }

        const float* rb = rows[buf];
        float vtl = rb[tl];
        float vtr = rb[tr];
        float vbl = rb[bl];
        float vbr = rb[br];
        if (ft) {   // essentially never taken
            vtl = __ldg(xn + (size_t)c*HW + yt*W_ + xl);
            vtr = __ldg(xn + (size_t)c*HW + yt*W_ + xr);
        }
        if (fb) {
            vbl = __ldg(xn + (size_t)c*HW + yb*W_ + xl);
            vbr = __ldg(xn + (size_t)c*HW + yb*W_ + xr);
        }

        float r = vtl*cw0;
        r = fmaf(vtr, cw1, r);
        r = fmaf(vbl, cw2, r);
        r = fmaf(vbr, cw3, r);
        op[(size_t)c*OH*OW] = r;

        __syncthreads();   // next buffer staged & this buffer's reads done
    }
}

// ---------------------------------------------------------------------------
extern "C" void kernel_launch(void* const* d_in, const int* in_sizes, int n_in,
                              void* d_out, int out_size)
{
    const float* x  = (const float*)d_in[0];
    const float* wt = (const float*)d_in[1];
    const float* bs = (const float*)d_in[2];
    float* out = (float*)d_out;

    conv_part_kernel<<<dim3(4, 4, 16), 256>>>(x, wt, bs);
    sample_kernel<<<N_*H_, 512>>>(x, out);
}

// round 7
// speedup vs baseline: 1.0837x; 1.0837x over previous
#include <cuda_runtime.h>
#include <cstdint>

#define N_  4
#define C_  128
#define H_  128
#define W_  128
#define OC  8
#define OH  256
#define OW  256
#define HW  (H_*W_)

typedef unsigned long long ull;

// Per-channel-group partial conv outputs: [cg][n][o][h][w]
__device__ float g_part[4][N_*OC*H_*W_];

// ---- f32x2 helpers ----
__device__ __forceinline__ ull pack2(float lo, float hi) {
    ull r;
    asm("mov.b64 %0, {%1, %2};" : "=l"(r) : "f"(lo), "f"(hi));
    return r;
}
__device__ __forceinline__ void unpack2(ull v, float& lo, float& hi) {
    asm("mov.b64 {%0, %1}, %2;" : "=f"(lo), "=f"(hi) : "l"(v));
}
__device__ __forceinline__ ull fma2(ull a, ull b, ull c) {
    ull d;
    asm("fma.rn.f32x2 %0, %1, %2, %3;" : "=l"(d) : "l"(a), "l"(b), "l"(c));
    return d;
}

// ---------------------------------------------------------------------------
// Kernel 1: 3x3 SAME conv, 32-channel partial per block (r2 structure,
// weights fetched as LDS.128 o-pairs). Grid (4,4,16), bz = n*4+cg.
// ---------------------------------------------------------------------------
__global__ __launch_bounds__(256) void conv_part_kernel(
    const float* __restrict__ x,
    const float* __restrict__ wt,    // [o][c][3][3]
    const float* __restrict__ bs)    // [o]
{
    __shared__ float xs[8*34*34];                  // 8 channels, 34x34 halo tile
    __shared__ __align__(16) ull ws2[8*9*8];       // [cc][tap][o], duplicated {w,w}

    const int tid = threadIdx.x;
    const int n  = blockIdx.z >> 2;
    const int cg = blockIdx.z & 3;
    const int h0 = blockIdx.y * 32;
    const int w0 = blockIdx.x * 32;
    const int tx  = tid & 31;
    const int ty0 = (tid >> 5) * 4;

    ull a01[OC], a23[OC];
    if (cg == 0) {
#pragma unroll
        for (int o = 0; o < OC; o++) {
            float b = __ldg(&bs[o]);
            a01[o] = pack2(b, b);
            a23[o] = a01[o];
        }
    } else {
#pragma unroll
        for (int o = 0; o < OC; o++) { a01[o] = 0ull; a23[o] = 0ull; }
    }

    const float* xn = x + ((size_t)n*C_ + cg*32) * HW;

    for (int ch = 0; ch < 4; ch++) {
        const int c0 = ch * 8;
        __syncthreads();
        for (int i = tid; i < 8*9*8; i += 256) {
            int cc = i / 72;
            int r  = i - cc*72;
            int tap = r >> 3;
            int o   = r & 7;
            float wv = wt[((size_t)o*C_ + (cg*32 + c0 + cc))*9 + tap];
            ws2[i] = pack2(wv, wv);
        }
        for (int i = tid; i < 8*34*34; i += 256) {
            int cc = i / 1156;
            int r  = i - cc*1156;
            int ly = r / 34;
            int lx = r - ly*34;
            int gy = h0 - 1 + ly;
            int gx = w0 - 1 + lx;
            float v = 0.f;
            if ((unsigned)gy < H_ && (unsigned)gx < W_)
                v = xn[(c0+cc)*HW + gy*W_ + gx];
            xs[i] = v;
        }
        __syncthreads();

#pragma unroll
        for (int cc = 0; cc < 8; cc++) {
            const float* xb = &xs[cc*1156 + ty0*34 + tx];
#pragma unroll
            for (int kx = 0; kx < 3; kx++) {
                float v[6];
#pragma unroll
                for (int r = 0; r < 6; r++)
                    v[r] = xb[r*34 + kx];
#pragma unroll
                for (int ky = 0; ky < 3; ky++) {
                    ull p01 = pack2(v[ky],   v[ky+1]);
                    ull p23 = pack2(v[ky+2], v[ky+3]);
                    const ulonglong2* wp =
                        reinterpret_cast<const ulonglong2*>(&ws2[cc*72 + (ky*3 + kx)*8]);
#pragma unroll
                    for (int q = 0; q < 4; q++) {
                        ulonglong2 w2 = wp[q];
                        a01[2*q  ] = fma2(p01, w2.x, a01[2*q  ]);
                        a23[2*q  ] = fma2(p23, w2.x, a23[2*q  ]);
                        a01[2*q+1] = fma2(p01, w2.y, a01[2*q+1]);
                        a23[2*q+1] = fma2(p23, w2.y, a23[2*q+1]);
                    }
                }
            }
        }
    }

    const int w = w0 + tx;
    float* gp = g_part[cg];
#pragma unroll
    for (int o = 0; o < OC; o++) {
        float r0, r1, r2, r3;
        unpack2(a01[o], r0, r1);
        unpack2(a23[o], r2, r3);
        size_t base = (((size_t)n*OC + o)*H_ + (h0 + ty0))*W_ + w;
        gp[base        ] = r0;
        gp[base +   W_ ] = r1;
        gp[base + 2*W_ ] = r2;
        gp[base + 3*W_ ] = r3;
    }
}

// ---------------------------------------------------------------------------
// Kernel 2: bilinear sampling + pixel shuffle, smem row-staged, 4 channels
// per pipeline round. One block per (n, h), 512 threads = 128w x 2kw x 2kh.
// Round: issue 4 staging LDGs -> compute 4 staged channels -> STS -> 1 sync.
// Rare out-of-window samples fall back to predicated __ldg.
// ---------------------------------------------------------------------------
#define RPAD 132
#define NROWS 8
#define CPC 4

__global__ __launch_bounds__(512) void sample_kernel(
    const float* __restrict__ x,
    float* __restrict__ out)
{
    __shared__ float soff[OC][W_];
    __shared__ float rows[2][CPC][NROWS*RPAD];

    const int b = blockIdx.x;
    const int n = b >> 7;
    const int h = b & (H_-1);
    const int tid = threadIdx.x;

    const int kw = tid & 1;
    const int w  = (tid >> 1) & (W_-1);
    const int kh = tid >> 8;

    // Staging geometry (constant across rounds)
    const int sr = (tid >> 6) & 7;     // staged row 0..7
    const int sc = (tid & 63) * 2;     // column pair
    const int sgy = h - 3 + sr;
    const bool srow_ok = ((unsigned)sgy < H_);
    const int stage_off = sr*RPAD + sc;
    const size_t stage_src = (size_t)sgy*W_ + sc;

    const float* xn = x + (size_t)n*C_*HW;

    // Stage offsets for row h (sum of 4 conv partials)
    for (int i = tid; i < OC*W_; i += 512) {
        int o  = i >> 7;
        int ww = i & (W_-1);
        size_t idx = (((size_t)n*OC + o)*H_ + h)*W_ + ww;
        soff[o][ww] = g_part[0][idx] + g_part[1][idx] + g_part[2][idx] + g_part[3][idx];
    }

    // Stage round 0 (channels 0..3) into buffer 0
    {
        float2 v[CPC];
#pragma unroll
        for (int cc = 0; cc < CPC; cc++)
            v[cc] = srow_ok
                ? *reinterpret_cast<const float2*>(xn + (size_t)cc*HW + stage_src)
                : make_float2(0.f, 0.f);
#pragma unroll
        for (int cc = 0; cc < CPC; cc++)
            *reinterpret_cast<float2*>(&rows[0][cc][stage_off]) = v[cc];
    }
    __syncthreads();

    // Per-thread sample geometry
    const int ob = (kh*2 + kw)*2;
    float sy = (float)h + soff[ob  ][w];
    float sx = (float)w + soff[ob+1][w];
    float y0f = floorf(sy), x0f = floorf(sx);
    int   y0 = (int)y0f,   x0 = (int)x0f;
    float fy = sy - y0f,   fx = sx - x0f;

    float cw0 = (1.f - fy) * (1.f - fx);
    float cw1 = (1.f - fy) * fx;
    float cw2 = fy * (1.f - fx);
    float cw3 = fy * fx;

    const int xl = min(max(x0,     0), W_-1);
    const int xr = min(max(x0 + 1, 0), W_-1);
    if (!((unsigned)x0       < (unsigned)W_)) { cw0 = 0.f; cw2 = 0.f; }
    if (!((unsigned)(x0 + 1) < (unsigned)W_)) { cw1 = 0.f; cw3 = 0.f; }

    const int yt = y0, yb = y0 + 1;
    if (!((unsigned)yt < (unsigned)H_)) { cw0 = 0.f; cw1 = 0.f; }
    if (!((unsigned)yb < (unsigned)H_)) { cw2 = 0.f; cw3 = 0.f; }

    int rst = min(max(yt - (h-3), 0), NROWS-1);
    int rsb = min(max(yb - (h-3), 0), NROWS-1);
    const bool ft = (yt != h-3+rst) && ((unsigned)yt < (unsigned)H_);
    const bool fb = (yb != h-3+rsb) && ((unsigned)yb < (unsigned)H_);
    const int tl = rst*RPAD + xl, tr = rst*RPAD + xr;
    const int bl = rsb*RPAD + xl, br = rsb*RPAD + xr;

    float* op = out + ((size_t)n*C_)*OH*OW + (size_t)(2*h + kh)*OW + (2*w + kw);

    for (int rnd = 0; rnd < C_/CPC; rnd++) {
        const int buf = rnd & 1;
        const int c0  = rnd * CPC;
        const bool more = (rnd + 1 < C_/CPC);

        // 1) issue next round's staging LDGs (latency hidden by compute below)
        float2 v[CPC];
        if (more) {
#pragma unroll
            for (int cc = 0; cc < CPC; cc++)
                v[cc] = srow_ok
                    ? *reinterpret_cast<const float2*>(xn + (size_t)(c0+CPC+cc)*HW + stage_src)
                    : make_float2(0.f, 0.f);
        }

        // 2) compute current 4 channels from smem
#pragma unroll
        for (int cc = 0; cc < CPC; cc++) {
            const float* rb = rows[buf][cc];
            float vtl = rb[tl];
            float vtr = rb[tr];
            float vbl = rb[bl];
            float vbr = rb[br];
            if (ft) {   // essentially never taken
                vtl = __ldg(xn + (size_t)(c0+cc)*HW + yt*W_ + xl);
                vtr = __ldg(xn + (size_t)(c0+cc)*HW + yt*W_ + xr);
            }
            if (fb) {
                vbl = __ldg(xn + (size_t)(c0+cc)*HW + yb*W_ + xl);
                vbr = __ldg(xn + (size_t)(c0+cc)*HW + yb*W_ + xr);
            }
            float r = vtl*cw0;
            r = fmaf(vtr, cw1, r);
            r = fmaf(vbl, cw2, r);
            r = fmaf(vbr, cw3, r);
            op[(size_t)(c0+cc)*OH*OW] = r;
        }

        // 3) commit staged data
        if (more) {
#pragma unroll
            for (int cc = 0; cc < CPC; cc++)
                *reinterpret_cast<float2*>(&rows[buf ^ 1][cc][stage_off]) = v[cc];
        }
        __syncthreads();
    }
}

// ---------------------------------------------------------------------------
extern "C" void kernel_launch(void* const* d_in, const int* in_sizes, int n_in,
                              void* d_out, int out_size)
{
    const float* x  = (const float*)d_in[0];
    const float* wt = (const float*)d_in[1];
    const float* bs = (const float*)d_in[2];
    float* out = (float*)d_out;

    conv_part_kernel<<<dim3(4, 4, 16), 256>>>(x, wt, bs);
    sample_kernel<<<N_*H_, 512>>>(x, out);
}

// round 8
// speedup vs baseline: 1.4534x; 1.3412x over previous
#include <cuda_runtime.h>
#include <cstdint>

#define N_  4
#define C_  128
#define H_  128
#define W_  128
#define OC  8
#define OH  256
#define OW  256
#define HW  (H_*W_)
#define NCG 8          // channel groups (16 ch each)

typedef unsigned long long ull;

// Per-channel-group partial conv outputs: [cg][n][o][h][w]
__device__ float g_part[NCG][N_*OC*H_*W_];

// ---- f32x2 helpers ----
__device__ __forceinline__ ull pack2(float lo, float hi) {
    ull r;
    asm("mov.b64 %0, {%1, %2};" : "=l"(r) : "f"(lo), "f"(hi));
    return r;
}
__device__ __forceinline__ void unpack2(ull v, float& lo, float& hi) {
    asm("mov.b64 {%0, %1}, %2;" : "=f"(lo), "=f"(hi) : "l"(v));
}
__device__ __forceinline__ ull fma2(ull a, ull b, ull c) {
    ull d;
    asm("fma.rn.f32x2 %0, %1, %2, %3;" : "=l"(d) : "l"(a), "l"(b), "l"(c));
    return d;
}

// ---------------------------------------------------------------------------
// Kernel 1: 3x3 SAME conv, 16-channel partial per block (r2 proven structure,
// finer channel split for wave balance). 256 threads, 32x32 tile, thread =
// 1 col x 4-row strip, f32x2 row pairs. Grid (4,4,32), bz = n*8+cg.
// ---------------------------------------------------------------------------
__global__ __launch_bounds__(256) void conv_part_kernel(
    const float* __restrict__ x,
    const float* __restrict__ wt,    // [o][c][3][3]
    const float* __restrict__ bs)    // [o]
{
    __shared__ float xs[8*34*34];    // 8 channels, 34x34 halo tile
    __shared__ ull ws2[8*9*8];       // [cc][tap][o], weight duplicated {w,w}

    const int tid = threadIdx.x;
    const int n  = blockIdx.z >> 3;
    const int cg = blockIdx.z & 7;
    const int h0 = blockIdx.y * 32;
    const int w0 = blockIdx.x * 32;
    const int tx  = tid & 31;
    const int ty0 = (tid >> 5) * 4;

    ull a01[OC], a23[OC];
    if (cg == 0) {
#pragma unroll
        for (int o = 0; o < OC; o++) {
            float b = __ldg(&bs[o]);
            a01[o] = pack2(b, b);
            a23[o] = a01[o];
        }
    } else {
#pragma unroll
        for (int o = 0; o < OC; o++) { a01[o] = 0ull; a23[o] = 0ull; }
    }

    const float* xn = x + ((size_t)n*C_ + cg*16) * HW;

    for (int ch = 0; ch < 2; ch++) {
        const int c0 = ch * 8;
        __syncthreads();
        // Stage chunk weights (duplicated to f32x2)
        for (int i = tid; i < 8*9*8; i += 256) {
            int cc = i / 72;
            int r  = i - cc*72;
            int tap = r >> 3;
            int o   = r & 7;
            float wv = wt[((size_t)o*C_ + (cg*16 + c0 + cc))*9 + tap];
            ws2[i] = pack2(wv, wv);
        }
        // Stage 8 channels of 34x34 halo tile (zero padded)
        for (int i = tid; i < 8*34*34; i += 256) {
            int cc = i / 1156;
            int r  = i - cc*1156;
            int ly = r / 34;
            int lx = r - ly*34;
            int gy = h0 - 1 + ly;
            int gx = w0 - 1 + lx;
            float v = 0.f;
            if ((unsigned)gy < H_ && (unsigned)gx < W_)
                v = xn[(c0+cc)*HW + gy*W_ + gx];
            xs[i] = v;
        }
        __syncthreads();

#pragma unroll
        for (int cc = 0; cc < 8; cc++) {
            const float* xb = &xs[cc*1156 + ty0*34 + tx];
#pragma unroll
            for (int kx = 0; kx < 3; kx++) {
                float v[6];
#pragma unroll
                for (int r = 0; r < 6; r++)
                    v[r] = xb[r*34 + kx];
#pragma unroll
                for (int ky = 0; ky < 3; ky++) {
                    ull p01 = pack2(v[ky],   v[ky+1]);
                    ull p23 = pack2(v[ky+2], v[ky+3]);
                    const ull* wp = &ws2[cc*72 + (ky*3 + kx)*8];
#pragma unroll
                    for (int o = 0; o < OC; o++) {
                        ull w2 = wp[o];
                        a01[o] = fma2(p01, w2, a01[o]);
                        a23[o] = fma2(p23, w2, a23[o]);
                    }
                }
            }
        }
    }

    const int w = w0 + tx;
    float* gp = g_part[cg];
#pragma unroll
    for (int o = 0; o < OC; o++) {
        float r0, r1, r2, r3;
        unpack2(a01[o], r0, r1);
        unpack2(a23[o], r2, r3);
        size_t base = (((size_t)n*OC + o)*H_ + (h0 + ty0))*W_ + w;
        gp[base        ] = r0;
        gp[base +   W_ ] = r1;
        gp[base + 2*W_ ] = r2;
        gp[base + 3*W_ ] = r3;
    }
}

// ---------------------------------------------------------------------------
// Kernel 2: bilinear sampling + pixel shuffle (r3 measured-best gather).
// One block per (n, h, kh): 256 threads, tid = w*2 + kw (one point/thread).
// Per channel: 4 LDG gathers, FMAs, one coalesced store; x2 unroll.
// ---------------------------------------------------------------------------
__global__ __launch_bounds__(256) void sample_kernel(
    const float* __restrict__ x,
    float* __restrict__ out)
{
    __shared__ float soff[4][W_];   // [kw*2+d][w] for this kh

    const int b  = blockIdx.x;
    const int kh = b & 1;
    const int h  = (b >> 1) & (H_-1);
    const int n  = b >> 8;
    const int tid = threadIdx.x;

    // Stage offsets for (n, h, kh): sum NCG conv partials
    for (int i = tid; i < 4*W_; i += 256) {
        int j  = i >> 7;
        int ww = i & (W_-1);
        int o  = (kh*2 + (j >> 1))*2 + (j & 1);
        size_t idx = (((size_t)n*OC + o)*H_ + h)*W_ + ww;
        float s = 0.f;
#pragma unroll
        for (int cg = 0; cg < NCG; cg++) s += g_part[cg][idx];
        soff[j][ww] = s;
    }
    __syncthreads();

    const int kw = tid & 1;
    const int w  = tid >> 1;

    float sy = (float)h + soff[kw*2    ][w];
    float sx = (float)w + soff[kw*2 + 1][w];
    float y0f = floorf(sy), x0f = floorf(sx);
    int   y0 = (int)y0f,   x0 = (int)x0f;
    float fy = sy - y0f,   fx = sx - x0f;

    float cw[4];
    cw[0] = (1.f - fy) * (1.f - fx);
    cw[1] = (1.f - fy) * fx;
    cw[2] = fy * (1.f - fx);
    cw[3] = fy * fx;
    int ci[4];
#pragma unroll
    for (int k = 0; k < 4; k++) {
        int yi = y0 + (k >> 1);
        int xi = x0 + (k & 1);
        bool valid = ((unsigned)yi < H_) && ((unsigned)xi < W_);
        int yc = min(max(yi, 0), H_-1);
        int xc = min(max(xi, 0), W_-1);
        ci[k] = yc*W_ + xc;
        if (!valid) cw[k] = 0.f;
    }

    const float* xp = x + (size_t)n*C_*HW;
    float* op = out + ((size_t)n*C_)*OH*OW + (size_t)(2*h + kh)*OW + (2*w + kw);

#pragma unroll 2
    for (int c = 0; c < C_; c++) {
        float v0 = __ldg(xp + ci[0]);
        float v1 = __ldg(xp + ci[1]);
        float v2 = __ldg(xp + ci[2]);
        float v3 = __ldg(xp + ci[3]);
        float r = v0*cw[0];
        r = fmaf(v1, cw[1], r);
        r = fmaf(v2, cw[2], r);
        r = fmaf(v3, cw[3], r);
        *op = r;
        xp += HW;
        op += OH*OW;
    }
}

// ---------------------------------------------------------------------------
extern "C" void kernel_launch(void* const* d_in, const int* in_sizes, int n_in,
                              void* d_out, int out_size)
{
    const float* x  = (const float*)d_in[0];
    const float* wt = (const float*)d_in[1];
    const float* bs = (const float*)d_in[2];
    float* out = (float*)d_out;

    conv_part_kernel<<<dim3(4, 4, 32), 256>>>(x, wt, bs);
    sample_kernel<<<N_*H_*2, 256>>>(x, out);
}